// round 4
// baseline (speedup 1.0000x reference)
#include <cuda_runtime.h>

#define NN 100000
#define NE 1600000

// ---------------- scratch (static device globals; no allocs) ----------------
__device__ int   g_cnt[NN];
__device__ int   g_off[NN + 1];
__device__ int   g_pos[NN];
__device__ int   g_srcs[NE];
__device__ float g_B0[128 * 256];              // [W_l0 | W_r0], row-major K=128 x 256
__device__ float g_B1[128 * 128];              // [W_l1 | W_r1], row-major K=128 x 128
__device__ float g_yz0[(size_t)NN * 256];      // x @ B0  (y0 = cols 0..127, z0 = 128..255)
__device__ float g_h[(size_t)NN * 128];        // relu'd layer-0 output
__device__ float g_yz1[(size_t)NN * 128];      // h @ B1  (y1 = cols 0..63, z1 = 64..127)

// ---------------- CSR build ----------------
__global__ void k_zero() {
    int i = blockIdx.x * blockDim.x + threadIdx.x;
    if (i < NN) g_cnt[i] = 0;
}

// edge_index is int32 (JAX x64 disabled: jnp.int64 request materializes as int32).
__global__ void k_count(const int* __restrict__ ei) {
    int e = blockIdx.x * blockDim.x + threadIdx.x;
    if (e < NE) {
        unsigned d = (unsigned)ei[NE + e];
        if (d < NN) atomicAdd(&g_cnt[d], 1);
    }
}

__global__ void k_scan() {
    __shared__ int sm[1024];
    int tid = threadIdx.x;
    const int CH = (NN + 1023) / 1024;
    int start = tid * CH;
    int end = min(start + CH, NN);
    int s = 0;
    for (int i = start; i < end; i++) s += g_cnt[i];
    sm[tid] = s;
    __syncthreads();
    for (int d = 1; d < 1024; d <<= 1) {
        int v = (tid >= d) ? sm[tid - d] : 0;
        __syncthreads();
        sm[tid] += v;
        __syncthreads();
    }
    int run = sm[tid] - s;  // exclusive prefix
    for (int i = start; i < end; i++) {
        g_off[i] = run;
        g_pos[i] = run;
        run += g_cnt[i];
    }
    if (tid == 0) g_off[NN] = run == run ? g_off[NN - 1] + g_cnt[NN - 1] : 0;
}

__global__ void k_scatter(const int* __restrict__ ei) {
    int e = blockIdx.x * blockDim.x + threadIdx.x;
    if (e < NE) {
        unsigned d = (unsigned)ei[NE + e];
        if (d < NN) {
            int p = atomicAdd(&g_pos[d], 1);
            unsigned s = (unsigned)ei[e];
            g_srcs[p] = (s < NN) ? (int)s : 0;
        }
    }
}

// ---------------- pack weights: B0 = [W_l0 | W_r0], B1 = [W_l1 | W_r1] ----------------
__global__ void k_pack(const float* __restrict__ Wl0, const float* __restrict__ Wr0,
                       const float* __restrict__ Wl1, const float* __restrict__ Wr1) {
    int i = blockIdx.x * blockDim.x + threadIdx.x;
    if (i < 128 * 256) {
        int k = i >> 8, j = i & 255;
        g_B0[i] = (j < 128) ? Wl0[k * 128 + j] : Wr0[k * 128 + (j - 128)];
    }
    if (i < 128 * 128) {
        int k = i >> 7, j = i & 127;
        g_B1[i] = (j < 64) ? Wl1[(k << 6) + j] : Wr1[(k << 6) + (j - 64)];
    }
}

// ---------------- fp32 SIMT GEMM: C[M,NB] = A[M,128] @ B[128,NB] ----------------
// BM=128, BN=128 tile, BK=8, 256 threads, 8x8 per thread (split 2x2 of 4-wide chunks).
template <int PHASE>
__global__ __launch_bounds__(256, 2) void k_gemm(const float* __restrict__ Ax, int M) {
    const float* __restrict__ A = (PHASE == 0) ? Ax : g_h;
    const float* __restrict__ B = (PHASE == 0) ? g_B0 : g_B1;
    float* __restrict__ C = (PHASE == 0) ? g_yz0 : g_yz1;
    const int NB = (PHASE == 0) ? 256 : 128;

    __shared__ float As[8][132];
    __shared__ float Bs[8][132];

    int tid = threadIdx.x;
    int m0 = blockIdx.x * 128;
    int n0 = blockIdx.y * 128;
    int tx = tid & 15, ty = tid >> 4;

    int aRow = tid >> 1;
    int aK = (tid & 1) * 4;
    int bRow = tid >> 5;
    int bCol = (tid & 31) * 4;

    float acc[2][2][4][4];
#pragma unroll
    for (int a = 0; a < 2; a++)
#pragma unroll
        for (int b = 0; b < 2; b++)
#pragma unroll
            for (int i = 0; i < 4; i++)
#pragma unroll
                for (int j = 0; j < 4; j++) acc[a][b][i][j] = 0.f;

    for (int k0 = 0; k0 < 128; k0 += 8) {
        float4 av = make_float4(0.f, 0.f, 0.f, 0.f);
        if (m0 + aRow < M) av = *(const float4*)&A[(size_t)(m0 + aRow) * 128 + k0 + aK];
        As[aK + 0][aRow] = av.x;
        As[aK + 1][aRow] = av.y;
        As[aK + 2][aRow] = av.z;
        As[aK + 3][aRow] = av.w;
        *(float4*)&Bs[bRow][bCol] = *(const float4*)&B[(size_t)(k0 + bRow) * NB + n0 + bCol];
        __syncthreads();

#pragma unroll
        for (int k = 0; k < 8; k++) {
            float4 a0 = *(const float4*)&As[k][ty * 4];
            float4 a1 = *(const float4*)&As[k][ty * 4 + 64];
            float4 b0 = *(const float4*)&Bs[k][tx * 4];
            float4 b1 = *(const float4*)&Bs[k][tx * 4 + 64];
            float ar[2][4] = {{a0.x, a0.y, a0.z, a0.w}, {a1.x, a1.y, a1.z, a1.w}};
            float br[2][4] = {{b0.x, b0.y, b0.z, b0.w}, {b1.x, b1.y, b1.z, b1.w}};
#pragma unroll
            for (int ii = 0; ii < 2; ii++)
#pragma unroll
                for (int jj = 0; jj < 2; jj++)
#pragma unroll
                    for (int i = 0; i < 4; i++)
#pragma unroll
                        for (int j = 0; j < 4; j++)
                            acc[ii][jj][i][j] = fmaf(ar[ii][i], br[jj][j], acc[ii][jj][i][j]);
        }
        __syncthreads();
    }

#pragma unroll
    for (int ii = 0; ii < 2; ii++)
#pragma unroll
        for (int i = 0; i < 4; i++) {
            int row = m0 + ty * 4 + ii * 64 + i;
            if (row < M) {
#pragma unroll
                for (int jj = 0; jj < 2; jj++) {
                    float4 v = make_float4(acc[ii][jj][i][0], acc[ii][jj][i][1],
                                           acc[ii][jj][i][2], acc[ii][jj][i][3]);
                    *(float4*)&C[(size_t)row * NB + n0 + tx * 4 + jj * 64] = v;
                }
            }
        }
}

// ---------------- layer-0 aggregate + bias + root + relu ----------------
// warp per node; lane handles 4 consecutive floats (float4) of the 128-wide row.
__global__ void k_agg1(const float* __restrict__ bias) {
    int node = blockIdx.x * 8 + (threadIdx.x >> 5);
    int lane = threadIdx.x & 31;
    if (node >= NN) return;
    int beg = g_off[node], end = g_off[node + 1];
    float inv = 1.0f / (float)max(end - beg, 1);
    float4 acc = make_float4(0.f, 0.f, 0.f, 0.f);
    for (int e = beg; e < end; e++) {
        int s = g_srcs[e];
        float4 v = *(const float4*)&g_yz0[(size_t)s * 256 + lane * 4];
        acc.x += v.x; acc.y += v.y; acc.z += v.z; acc.w += v.w;
    }
    float4 z = *(const float4*)&g_yz0[(size_t)node * 256 + 128 + lane * 4];
    float4 b = *(const float4*)&bias[lane * 4];
    float4 r;
    r.x = fmaxf(fmaf(acc.x, inv, b.x + z.x), 0.f);
    r.y = fmaxf(fmaf(acc.y, inv, b.y + z.y), 0.f);
    r.z = fmaxf(fmaf(acc.z, inv, b.z + z.z), 0.f);
    r.w = fmaxf(fmaf(acc.w, inv, b.w + z.w), 0.f);
    *(float4*)&g_h[(size_t)node * 128 + lane * 4] = r;
}

// ---------------- layer-1 aggregate + bias + root ----------------
// warp per node; lane handles 2 consecutive floats (float2) of the 64-wide row.
__global__ void k_agg2(const float* __restrict__ bias, float* __restrict__ out) {
    int node = blockIdx.x * 8 + (threadIdx.x >> 5);
    int lane = threadIdx.x & 31;
    if (node >= NN) return;
    int beg = g_off[node], end = g_off[node + 1];
    float inv = 1.0f / (float)max(end - beg, 1);
    float2 acc = make_float2(0.f, 0.f);
    for (int e = beg; e < end; e++) {
        int s = g_srcs[e];
        float2 v = *(const float2*)&g_yz1[(size_t)s * 128 + lane * 2];
        acc.x += v.x; acc.y += v.y;
    }
    float2 z = *(const float2*)&g_yz1[(size_t)node * 128 + 64 + lane * 2];
    float2 b = *(const float2*)&bias[lane * 2];
    float2 r;
    r.x = fmaf(acc.x, inv, b.x + z.x);
    r.y = fmaf(acc.y, inv, b.y + z.y);
    *(float2*)&out[(size_t)node * 64 + lane * 2] = r;
}

// ---------------- launch ----------------
extern "C" void kernel_launch(void* const* d_in, const int* in_sizes, int n_in,
                              void* d_out, int out_size) {
    const float* x = (const float*)d_in[0];
    const int* ei = (const int*)d_in[1];          // int32 edge_index [2, NE]
    const float* Wl0 = (const float*)d_in[2];
    const float* bl0 = (const float*)d_in[3];
    const float* Wr0 = (const float*)d_in[4];
    const float* Wl1 = (const float*)d_in[5];
    const float* bl1 = (const float*)d_in[6];
    const float* Wr1 = (const float*)d_in[7];
    float* out = (float*)d_out;

    // CSR build (every launch; graph-replay safe)
    k_zero<<<(NN + 255) / 256, 256>>>();
    k_count<<<(NE + 255) / 256, 256>>>(ei);
    k_scan<<<1, 1024>>>();
    k_scatter<<<(NE + 255) / 256, 256>>>(ei);
    k_pack<<<(128 * 256 + 255) / 256, 256>>>(Wl0, Wr0, Wl1, Wr1);

    int mt = (NN + 127) / 128;  // 782
    // Layer 0: yz0 = x @ [W_l0 | W_r0]
    k_gemm<0><<<dim3(mt, 2), 256>>>(x, NN);
    // h = relu(mean_agg(y0) + b0 + z0)
    k_agg1<<<(NN + 7) / 8, 256>>>(bl0);
    // Layer 1: yz1 = h @ [W_l1 | W_r1]
    k_gemm<1><<<dim3(mt, 1), 256>>>(nullptr, NN);
    // out = mean_agg(y1) + b1 + z1
    k_agg2<<<(NN + 7) / 8, 256>>>(bl1, out);
}

// round 5
// speedup vs baseline: 1.0231x; 1.0231x over previous
#include <cuda_runtime.h>

#define NN 100000
#define NE 1600000

typedef unsigned long long u64;

// ---------------- scratch (static device globals; no allocs) ----------------
__device__ int   g_cnt[NN];
__device__ int   g_off[NN + 1];
__device__ int   g_pos[NN];
__device__ int   g_srcs[NE];
__device__ float g_B0[128 * 256];              // [W_l0 | W_r0], row-major K=128 x 256
__device__ float g_B1[128 * 128];              // [W_l1 | W_r1], row-major K=128 x 128
__device__ float g_yz0[(size_t)NN * 256];      // x @ B0  (y0 = cols 0..127, z0 = 128..255)
__device__ float g_h[(size_t)NN * 128];        // relu'd layer-0 output
__device__ float g_yz1[(size_t)NN * 128];      // h @ B1  (y1 = cols 0..63, z1 = 64..127)

// ---------------- packed f32x2 helpers (sm_103a FFMA2 path) ----------------
__device__ __forceinline__ u64 pack2(float lo, float hi) {
    u64 r;
    asm("mov.b64 %0, {%1, %2};" : "=l"(r) : "r"(__float_as_uint(lo)), "r"(__float_as_uint(hi)));
    return r;
}
__device__ __forceinline__ u64 dup2(float v) {
    u64 r;
    unsigned u = __float_as_uint(v);
    asm("mov.b64 %0, {%1, %1};" : "=l"(r) : "r"(u));
    return r;
}
__device__ __forceinline__ void fma2(u64& d, u64 a, u64 b) {
    asm("fma.rn.f32x2 %0, %1, %2, %3;" : "=l"(d) : "l"(a), "l"(b), "l"(d));
}
__device__ __forceinline__ float2 unpack2(u64 v) {
    unsigned lo, hi;
    asm("mov.b64 {%0, %1}, %2;" : "=r"(lo), "=r"(hi) : "l"(v));
    return make_float2(__uint_as_float(lo), __uint_as_float(hi));
}

// ---------------- CSR build ----------------
__global__ void k_zero() {
    int i = blockIdx.x * blockDim.x + threadIdx.x;
    if (i < NN) g_cnt[i] = 0;
}

// edge_index is int32 (JAX x64 disabled: jnp.int64 request materializes as int32).
__global__ void k_count(const int* __restrict__ ei) {
    int e = blockIdx.x * blockDim.x + threadIdx.x;
    if (e < NE) {
        unsigned d = (unsigned)ei[NE + e];
        if (d < NN) atomicAdd(&g_cnt[d], 1);
    }
}

__global__ void k_scan() {
    __shared__ int sm[1024];
    int tid = threadIdx.x;
    const int CH = (NN + 1023) / 1024;
    int start = tid * CH;
    int end = min(start + CH, NN);
    int s = 0;
    for (int i = start; i < end; i++) s += g_cnt[i];
    sm[tid] = s;
    __syncthreads();
    for (int d = 1; d < 1024; d <<= 1) {
        int v = (tid >= d) ? sm[tid - d] : 0;
        __syncthreads();
        sm[tid] += v;
        __syncthreads();
    }
    int run = sm[tid] - s;  // exclusive prefix
    for (int i = start; i < end; i++) {
        g_off[i] = run;
        g_pos[i] = run;
        run += g_cnt[i];
    }
    if (tid == 1023) g_off[NN] = run;  // total count (race-free: own value)
}

__global__ void k_scatter(const int* __restrict__ ei) {
    int e = blockIdx.x * blockDim.x + threadIdx.x;
    if (e < NE) {
        unsigned d = (unsigned)ei[NE + e];
        if (d < NN) {
            int p = atomicAdd(&g_pos[d], 1);
            unsigned s = (unsigned)ei[e];
            g_srcs[p] = (s < NN) ? (int)s : 0;
        }
    }
}

// ---------------- pack weights: B0 = [W_l0 | W_r0], B1 = [W_l1 | W_r1] ----------------
__global__ void k_pack(const float* __restrict__ Wl0, const float* __restrict__ Wr0,
                       const float* __restrict__ Wl1, const float* __restrict__ Wr1) {
    int i = blockIdx.x * blockDim.x + threadIdx.x;
    if (i < 128 * 256) {
        int k = i >> 8, j = i & 255;
        g_B0[i] = (j < 128) ? Wl0[k * 128 + j] : Wr0[k * 128 + (j - 128)];
    }
    if (i < 128 * 128) {
        int k = i >> 7, j = i & 127;
        g_B1[i] = (j < 64) ? Wl1[(k << 6) + j] : Wr1[(k << 6) + (j - 64)];
    }
}

// ---------------- fp32 GEMM with packed FFMA2: C[M,NB] = A[M,128] @ B[128,NB] ----------------
// BM=128, BN=128, BK=8, 256 threads, 8 rows x 8 cols (4 f32x2 pairs) per thread.
template <int PHASE>
__global__ __launch_bounds__(256, 2) void k_gemm(const float* __restrict__ Ax, int M) {
    const float* __restrict__ A = (PHASE == 0) ? Ax : g_h;
    const float* __restrict__ B = (PHASE == 0) ? g_B0 : g_B1;
    float* __restrict__ C = (PHASE == 0) ? g_yz0 : g_yz1;
    const int NB = (PHASE == 0) ? 256 : 128;

    __shared__ float As[8][132];
    __shared__ float Bs[8][132];

    int tid = threadIdx.x;
    int m0 = blockIdx.x * 128;
    int n0 = blockIdx.y * 128;
    int tx = tid & 15, ty = tid >> 4;

    int aRow = tid >> 1;
    int aK = (tid & 1) * 4;
    int bRow = tid >> 5;
    int bCol = (tid & 31) * 4;

    // acc[i][j]: i = row (0..3 -> ty*4+i, 4..7 -> ty*4+64+i-4); j = col pair
    // (0..1 -> tx*4 + 2j, 2..3 -> tx*4 + 64 + 2(j-2))
    u64 acc[8][4];
#pragma unroll
    for (int i = 0; i < 8; i++)
#pragma unroll
        for (int j = 0; j < 4; j++) acc[i][j] = 0ull;

    for (int k0 = 0; k0 < 128; k0 += 8) {
        float4 av = make_float4(0.f, 0.f, 0.f, 0.f);
        if (m0 + aRow < M) av = *(const float4*)&A[(size_t)(m0 + aRow) * 128 + k0 + aK];
        As[aK + 0][aRow] = av.x;
        As[aK + 1][aRow] = av.y;
        As[aK + 2][aRow] = av.z;
        As[aK + 3][aRow] = av.w;
        *(float4*)&Bs[bRow][bCol] = *(const float4*)&B[(size_t)(k0 + bRow) * NB + n0 + bCol];
        __syncthreads();

#pragma unroll
        for (int k = 0; k < 8; k++) {
            float4 a0 = *(const float4*)&As[k][ty * 4];
            float4 a1 = *(const float4*)&As[k][ty * 4 + 64];
            float4 b0 = *(const float4*)&Bs[k][tx * 4];
            float4 b1 = *(const float4*)&Bs[k][tx * 4 + 64];
            u64 bp[4] = {pack2(b0.x, b0.y), pack2(b0.z, b0.w),
                         pack2(b1.x, b1.y), pack2(b1.z, b1.w)};
            float ar[8] = {a0.x, a0.y, a0.z, a0.w, a1.x, a1.y, a1.z, a1.w};
#pragma unroll
            for (int i = 0; i < 8; i++) {
                u64 ad = dup2(ar[i]);
#pragma unroll
                for (int j = 0; j < 4; j++) fma2(acc[i][j], ad, bp[j]);
            }
        }
        __syncthreads();
    }

#pragma unroll
    for (int i = 0; i < 8; i++) {
        int row = m0 + ty * 4 + (i & 3) + (i >> 2) * 64;
        if (row < M) {
#pragma unroll
            for (int g = 0; g < 2; g++) {
                float2 lo = unpack2(acc[i][g * 2 + 0]);
                float2 hi = unpack2(acc[i][g * 2 + 1]);
                float4 v = make_float4(lo.x, lo.y, hi.x, hi.y);
                *(float4*)&C[(size_t)row * NB + n0 + tx * 4 + g * 64] = v;
            }
        }
    }
}

// ---------------- layer-0 aggregate + bias + root + relu ----------------
__global__ void k_agg1(const float* __restrict__ bias) {
    int node = blockIdx.x * 8 + (threadIdx.x >> 5);
    int lane = threadIdx.x & 31;
    if (node >= NN) return;
    int beg = g_off[node], end = g_off[node + 1];
    float inv = 1.0f / (float)max(end - beg, 1);
    float4 acc = make_float4(0.f, 0.f, 0.f, 0.f);
    for (int e = beg; e < end; e++) {
        int s = g_srcs[e];
        float4 v = *(const float4*)&g_yz0[(size_t)s * 256 + lane * 4];
        acc.x += v.x; acc.y += v.y; acc.z += v.z; acc.w += v.w;
    }
    float4 z = *(const float4*)&g_yz0[(size_t)node * 256 + 128 + lane * 4];
    float4 b = *(const float4*)&bias[lane * 4];
    float4 r;
    r.x = fmaxf(fmaf(acc.x, inv, b.x + z.x), 0.f);
    r.y = fmaxf(fmaf(acc.y, inv, b.y + z.y), 0.f);
    r.z = fmaxf(fmaf(acc.z, inv, b.z + z.z), 0.f);
    r.w = fmaxf(fmaf(acc.w, inv, b.w + z.w), 0.f);
    *(float4*)&g_h[(size_t)node * 128 + lane * 4] = r;
}

// ---------------- layer-1 aggregate + bias + root ----------------
__global__ void k_agg2(const float* __restrict__ bias, float* __restrict__ out) {
    int node = blockIdx.x * 8 + (threadIdx.x >> 5);
    int lane = threadIdx.x & 31;
    if (node >= NN) return;
    int beg = g_off[node], end = g_off[node + 1];
    float inv = 1.0f / (float)max(end - beg, 1);
    float2 acc = make_float2(0.f, 0.f);
    for (int e = beg; e < end; e++) {
        int s = g_srcs[e];
        float2 v = *(const float2*)&g_yz1[(size_t)s * 128 + lane * 2];
        acc.x += v.x; acc.y += v.y;
    }
    float2 z = *(const float2*)&g_yz1[(size_t)node * 128 + 64 + lane * 2];
    float2 b = *(const float2*)&bias[lane * 2];
    float2 r;
    r.x = fmaf(acc.x, inv, b.x + z.x);
    r.y = fmaf(acc.y, inv, b.y + z.y);
    *(float2*)&out[(size_t)node * 64 + lane * 2] = r;
}

// ---------------- launch ----------------
extern "C" void kernel_launch(void* const* d_in, const int* in_sizes, int n_in,
                              void* d_out, int out_size) {
    const float* x = (const float*)d_in[0];
    const int* ei = (const int*)d_in[1];          // int32 edge_index [2, NE]
    const float* Wl0 = (const float*)d_in[2];
    const float* bl0 = (const float*)d_in[3];
    const float* Wr0 = (const float*)d_in[4];
    const float* Wl1 = (const float*)d_in[5];
    const float* bl1 = (const float*)d_in[6];
    const float* Wr1 = (const float*)d_in[7];
    float* out = (float*)d_out;

    // CSR build (every launch; graph-replay safe)
    k_zero<<<(NN + 255) / 256, 256>>>();
    k_count<<<(NE + 255) / 256, 256>>>(ei);
    k_scan<<<1, 1024>>>();
    k_scatter<<<(NE + 255) / 256, 256>>>(ei);
    k_pack<<<(128 * 256 + 255) / 256, 256>>>(Wl0, Wr0, Wl1, Wr1);

    int mt = (NN + 127) / 128;  // 782
    // Layer 0: yz0 = x @ [W_l0 | W_r0]
    k_gemm<0><<<dim3(mt, 2), 256>>>(x, NN);
    // h = relu(mean_agg(y0) + b0 + z0)
    k_agg1<<<(NN + 7) / 8, 256>>>(bl0);
    // Layer 1: yz1 = h @ [W_l1 | W_r1]
    k_gemm<1><<<dim3(mt, 1), 256>>>(nullptr, NN);
    // out = mean_agg(y1) + b1 + z1
    k_agg2<<<(NN + 7) / 8, 256>>>(bl1, out);
}